// round 1
// baseline (speedup 1.0000x reference)
#include <cuda_runtime.h>

#define NPIX  65536      // 64 * 32 * 32 pixels
#define KCODE 1024
#define DDIM  256
#define HW    1024       // 32*32, pixels per batch image

#define BM 128
#define BN 128
#define BK 16
#define BNS 132          // padded Bs row stride (store-conflict mitigation, keeps 16B align)

__device__ unsigned long long g_keys[NPIX];
__device__ float g_esq[KCODE];
__device__ float g_sf[NPIX];
__device__ float g_loss;

// ---------- helpers ----------
__device__ __forceinline__ unsigned f2ord(float f) {
    unsigned u = __float_as_uint(f);
    return (u & 0x80000000u) ? ~u : (u | 0x80000000u);
}
__device__ __forceinline__ unsigned long long pack_dup(float x) {
    unsigned long long r;
    asm("mov.b64 %0, {%1, %1};" : "=l"(r) : "f"(x));
    return r;
}
__device__ __forceinline__ void fma2(unsigned long long& d,
                                     unsigned long long a,
                                     unsigned long long b) {
    asm("fma.rn.f32x2 %0, %1, %2, %0;" : "+l"(d) : "l"(a), "l"(b));
}
__device__ __forceinline__ float2 unpack2(unsigned long long v) {
    float2 f;
    asm("mov.b64 {%0, %1}, %2;" : "=f"(f.x), "=f"(f.y) : "l"(v));
    return f;
}

// ---------- init: argmin keys to +inf, loss accumulator to 0 ----------
__global__ void k_init() {
    int i = blockIdx.x * 256 + threadIdx.x;
    g_keys[i] = ~0ULL;
    if (i == 0) g_loss = 0.f;
}

// ---------- ||e_k||^2, one warp per code row ----------
__global__ void k_esq(const float* __restrict__ emb) {
    int w    = (blockIdx.x * blockDim.x + threadIdx.x) >> 5;   // code id 0..1023
    int lane = threadIdx.x & 31;
    const float* row = emb + (size_t)w * DDIM;
    float s = 0.f;
#pragma unroll
    for (int j = 0; j < 8; ++j) { float v = row[lane + 32 * j]; s = fmaf(v, v, s); }
#pragma unroll
    for (int sh = 16; sh; sh >>= 1) s += __shfl_xor_sync(0xffffffffu, s, sh);
    if (lane == 0) g_esq[w] = s;
}

// ---------- ||f_n||^2, coalesced strided reduction over channels ----------
__global__ void k_sf(const float* __restrict__ lat) {
    int n = blockIdx.x * 256 + threadIdx.x;
    int b = n >> 10, p = n & 1023;
    const float* base = lat + (size_t)b * DDIM * HW + p;
    float s = 0.f;
#pragma unroll 4
    for (int d = 0; d < DDIM; ++d) { float v = base[(size_t)d * HW]; s = fmaf(v, v, s); }
    g_sf[n] = s;
}

// ---------- fused distance GEMM (f32x2 packed FMA) + argmin ----------
// Tile: 128 pixels x 128 codes, reduce over D=256 in BK=16 chunks.
// 256 threads, each owns an 8x8 micro-tile held as 8x4 packed f32x2 accumulators.
__global__ void __launch_bounds__(256, 2)
k_dist(const float* __restrict__ lat, const float* __restrict__ emb) {
    __shared__ __align__(16) float As[BK * BM];
    __shared__ __align__(16) float Bs[BK * BNS];

    const int tid = threadIdx.x;
    const int tx = tid & 15, ty = tid >> 4;
    const int n0 = blockIdx.x * BM;
    const int b  = n0 >> 10;
    const int p0 = n0 & 1023;
    const int c0 = blockIdx.y * BN;
    const float* Ab = lat + (size_t)b * DDIM * HW + p0;
    const float* Bb = emb + (size_t)c0 * DDIM;

    // load mappings (coalesced)
    const int aD = tid >> 5;          // 0..7   (d within chunk, two passes: aD, aD+8)
    const int aM = (tid & 31) << 2;   // 0..124 (pixel, float4)
    const int bN = tid >> 2;          // 0..63  (code, two passes: bN, bN+64)
    const int bD = (tid & 3) << 2;    // 0,4,8,12 (d, float4)

    unsigned long long acc[8][4];
#pragma unroll
    for (int i = 0; i < 8; ++i)
#pragma unroll
        for (int j = 0; j < 4; ++j) acc[i][j] = 0ULL;

    // register-staged prefetch
    float4 sa0 = *(const float4*)(Ab + (size_t)aD * HW + aM);
    float4 sa1 = *(const float4*)(Ab + (size_t)(aD + 8) * HW + aM);
    float4 sb0 = *(const float4*)(Bb + (size_t)bN * DDIM + bD);
    float4 sb1 = *(const float4*)(Bb + (size_t)(bN + 64) * DDIM + bD);

    for (int it = 0; it < DDIM / BK; ++it) {
        *(float4*)(As + aD * BM + aM)       = sa0;
        *(float4*)(As + (aD + 8) * BM + aM) = sa1;
        Bs[(bD + 0) * BNS + bN] = sb0.x;
        Bs[(bD + 1) * BNS + bN] = sb0.y;
        Bs[(bD + 2) * BNS + bN] = sb0.z;
        Bs[(bD + 3) * BNS + bN] = sb0.w;
        Bs[(bD + 0) * BNS + bN + 64] = sb1.x;
        Bs[(bD + 1) * BNS + bN + 64] = sb1.y;
        Bs[(bD + 2) * BNS + bN + 64] = sb1.z;
        Bs[(bD + 3) * BNS + bN + 64] = sb1.w;
        __syncthreads();
        if (it + 1 < DDIM / BK) {
            int d0 = (it + 1) * BK;
            sa0 = *(const float4*)(Ab + (size_t)(d0 + aD) * HW + aM);
            sa1 = *(const float4*)(Ab + (size_t)(d0 + aD + 8) * HW + aM);
            sb0 = *(const float4*)(Bb + (size_t)bN * DDIM + d0 + bD);
            sb1 = *(const float4*)(Bb + (size_t)(bN + 64) * DDIM + d0 + bD);
        }
#pragma unroll
        for (int d = 0; d < BK; ++d) {
            const float* ap = As + d * BM + (ty << 3);
            float4 a0 = *(const float4*)ap;
            float4 a1 = *(const float4*)(ap + 4);
            const double2* bp = (const double2*)(Bs + d * BNS + (tx << 3));
            double2 b01 = bp[0], b23 = bp[1];
            unsigned long long rn[4] = {
                __double_as_longlong(b01.x), __double_as_longlong(b01.y),
                __double_as_longlong(b23.x), __double_as_longlong(b23.y) };
            float am[8] = { a0.x, a0.y, a0.z, a0.w, a1.x, a1.y, a1.z, a1.w };
#pragma unroll
            for (int i = 0; i < 8; ++i) {
                unsigned long long rm = pack_dup(am[i]);
#pragma unroll
                for (int j = 0; j < 4; ++j) fma2(acc[i][j], rm, rn[j]);
            }
        }
        __syncthreads();
    }

    // epilogue: replicate reference rounding chain fl(fl(sf+se) - 2*dot),
    // pack (orderable(score), code) keys, per-row min, atomicMin merge.
#pragma unroll
    for (int i = 0; i < 8; ++i) {
        int row  = n0 + (ty << 3) + i;
        float sf = g_sf[row];
        unsigned long long best = ~0ULL;
#pragma unroll
        for (int j = 0; j < 4; ++j) {
            float2 dd = unpack2(acc[i][j]);
            int c = c0 + (tx << 3) + (j << 1);
            float t0 = sf + g_esq[c];          // fl(sf + se)  (matches ref broadcast-add)
            float t1 = sf + g_esq[c + 1];
            float s0 = fmaf(-2.f, dd.x, t0);   // == fl(t - 2*dot), 2*dot exact
            float s1 = fmaf(-2.f, dd.y, t1);
            unsigned long long k0 = ((unsigned long long)f2ord(s0) << 32) | (unsigned)c;
            unsigned long long k1 = ((unsigned long long)f2ord(s1) << 32) | (unsigned)(c + 1);
            if (k1 < k0) k0 = k1;
            if (k0 < best) best = k0;
        }
#pragma unroll
        for (int sh = 8; sh; sh >>= 1) {       // reduce across the 16 tx lanes (half-warp)
            unsigned long long o = __shfl_xor_sync(0xffffffffu, best, sh);
            if (o < best) best = o;
        }
        if (tx == 0) atomicMin(&g_keys[row], best);
    }
}

// ---------- gather + transposed write + fused MSE reduction ----------
// Each block: 32 pixels. Stage 32 codebook rows in smem, then write out[b,d,h,w]
// coalescing over pixels, accumulating sum((quant-lat)^2).
__global__ void k_gather(const float* __restrict__ lat, const float* __restrict__ emb,
                         float* __restrict__ out) {
    __shared__ __align__(16) float rows[32 * 260];
    __shared__ int sInd[32];
    const int t  = threadIdx.x;
    const int n0 = blockIdx.x << 5;
    const int b  = n0 >> 10, p0 = n0 & 1023;

    if (t < 32) sInd[t] = (int)(unsigned)(g_keys[n0 + t]);   // low 32 bits = code index
    __syncthreads();
#pragma unroll
    for (int i = 0; i < 8; ++i) {
        int idx4 = t + (i << 8);
        int r = idx4 >> 6, c4 = (idx4 & 63) << 2;
        float4 v = *(const float4*)(emb + (size_t)sInd[r] * DDIM + c4);
        *(float4*)(rows + r * 260 + c4) = v;
    }
    __syncthreads();

    const int i = t & 31, db = t >> 5;
    float accl = 0.f;
#pragma unroll
    for (int dd = 0; dd < 32; ++dd) {
        int d = (dd << 3) + db;
        size_t gi = ((size_t)(b * DDIM + d)) * HW + p0 + i;
        float q = rows[i * 260 + d];
        float l = lat[gi];
        out[gi] = q;                      // straight-through output == quant
        float df = q - l;
        accl = fmaf(df, df, accl);
    }
#pragma unroll
    for (int sh = 16; sh; sh >>= 1) accl += __shfl_xor_sync(0xffffffffu, accl, sh);
    if ((t & 31) == 0) atomicAdd(&g_loss, accl);
}

// ---------- scalars ----------
__global__ void k_final(float* __restrict__ out, int off) {
    float S = g_loss * (1.0f / 16777216.0f);   // mean over N*D elements
    out[off]     = S;          // embedding_loss
    out[off + 1] = 0.25f * S;  // BETA * commitment_loss (numerically identical mean)
}

extern "C" void kernel_launch(void* const* d_in, const int* in_sizes, int n_in,
                              void* d_out, int out_size) {
    const float* lat = (const float*)d_in[0];   // latents [64,256,32,32]
    const float* emb = (const float*)d_in[1];   // embedding [1024,256]
    float* out = (float*)d_out;

    k_init<<<NPIX / 256, 256>>>();
    k_esq<<<KCODE / 8, 256>>>(emb);
    k_sf<<<NPIX / 256, 256>>>(lat);
    k_dist<<<dim3(NPIX / BM, KCODE / BN), 256>>>(lat, emb);
    k_gather<<<NPIX / 32, 256>>>(lat, emb, out);
    if (out_size >= NPIX * DDIM + 2) {
        k_final<<<1, 1>>>(out, out_size - 2);
    }
}